// round 1
// baseline (speedup 1.0000x reference)
#include <cuda_runtime.h>
#include <cstdint>

#define ITEM_NUM 100000
#define DIM 64
#define BS 256
#define NC 5

#define IT 64      // items per CTA tile
#define UT 16      // users per CTA tile
#define THREADS 128

// Precomputed A[u][d][c] = user_emb[u][d] * W[c][d], padded to 8 floats per (u,d)
// for aligned float4 smem staging. 256*64*8*4 = 512 KB static device scratch.
__device__ float g_A[BS * DIM * 8];

__global__ void precompute_kernel(const void* __restrict__ batch_user,
                                  const float* __restrict__ user_table,
                                  const float* __restrict__ cls_w) {
    int u = blockIdx.x;   // 0..255
    int d = threadIdx.x;  // 0..63

    // Runtime int64-vs-int32 detection: if int64, high words of ids (<100000) are 0.
    const unsigned* q = (const unsigned*)batch_user;
    bool is64 = ((q[1] | q[3] | q[5] | q[7]) == 0u);
    long long idx;
    if (is64) idx = ((const long long*)batch_user)[u];
    else      idx = (long long)((const int*)batch_user)[u];

    float uv = user_table[idx * DIM + d];
    float* dst = g_A + ((size_t)u * DIM + d) * 8;
#pragma unroll
    for (int c = 0; c < NC; c++) dst[c] = uv * cls_w[c * DIM + d];
    dst[5] = 0.f; dst[6] = 0.f; dst[7] = 0.f;
}

// ---- packed f32x2 helpers (sm_100+; ptxas never emits FFMA2 from C++) ----
__device__ __forceinline__ unsigned long long ffma2(unsigned long long a,
                                                    unsigned long long b,
                                                    unsigned long long c) {
    unsigned long long d;
    asm("fma.rn.f32x2 %0, %1, %2, %3;" : "=l"(d) : "l"(a), "l"(b), "l"(c));
    return d;
}
__device__ __forceinline__ unsigned long long dup2(float a) {
    unsigned long long d;
    asm("mov.b64 %0, {%1, %1};" : "=l"(d) : "f"(a));
    return d;
}
__device__ __forceinline__ float2 unpack2(unsigned long long v) {
    float2 r;
    asm("mov.b64 {%0, %1}, %2;" : "=f"(r.x), "=f"(r.y) : "l"(v));
    return r;
}

__global__ __launch_bounds__(THREADS) void score_kernel(
    const float* __restrict__ item_table,
    const float* __restrict__ cls_b,
    const float* __restrict__ values,
    float* __restrict__ out)
{
    __shared__ float s_items[DIM][IT];        // transposed item tile: 16 KB
    __shared__ float s_A[UT * DIM * 8];       // padded A tile:        32 KB

    const int i0  = blockIdx.x * IT;
    const int u0  = blockIdx.y * UT;
    const int tid = threadIdx.x;

    // Load item tile [IT x DIM] transposed into smem [d][i].
    for (int idx = tid; idx < IT * (DIM / 4); idx += THREADS) {
        int i  = idx >> 4;        // item within tile
        int dc = idx & 15;        // d-chunk of 4
        int gi = i0 + i;
        float4 v = make_float4(0.f, 0.f, 0.f, 0.f);
        if (gi < ITEM_NUM)
            v = *(const float4*)(item_table + (size_t)gi * DIM + dc * 4);
        s_items[dc * 4 + 0][i] = v.x;
        s_items[dc * 4 + 1][i] = v.y;
        s_items[dc * 4 + 2][i] = v.z;
        s_items[dc * 4 + 3][i] = v.w;
    }
    // Stage A tile for UT users (vectorized copy).
    {
        const float4* src = (const float4*)(g_A + (size_t)u0 * DIM * 8);
        float4* dst = (float4*)s_A;
        for (int idx = tid; idx < UT * DIM * 2; idx += THREADS)
            dst[idx] = src[idx];
    }
    __syncthreads();

    const int u  = tid >> 3;           // 0..15 : user within tile
    const int ib = (tid & 7) * 8;      // 0..56 : item base within tile (8 items/thread)

    const float* sIt = &s_items[0][ib];
    const float* sAu = s_A + u * DIM * 8;

    unsigned long long acc[4][NC];     // 4 item-pairs x 5 classes, packed f32x2
#pragma unroll
    for (int jp = 0; jp < 4; jp++)
#pragma unroll
        for (int c = 0; c < NC; c++) acc[jp][c] = 0ull;

#pragma unroll 8
    for (int k = 0; k < DIM; k++) {
        ulonglong2 p0 = *(const ulonglong2*)(sIt + k * IT);       // items ib..ib+3
        ulonglong2 p1 = *(const ulonglong2*)(sIt + k * IT + 4);   // items ib+4..ib+7
        float4 a03 = *(const float4*)(sAu + k * 8);
        float  a4f = sAu[k * 8 + 4];
        unsigned long long a2[NC] = { dup2(a03.x), dup2(a03.y), dup2(a03.z),
                                      dup2(a03.w), dup2(a4f) };
        unsigned long long it2[4] = { p0.x, p0.y, p1.x, p1.y };
#pragma unroll
        for (int jp = 0; jp < 4; jp++)
#pragma unroll
            for (int c = 0; c < NC; c++)
                acc[jp][c] = ffma2(a2[c], it2[jp], acc[jp][c]);
    }

    // Epilogue: 5-way softmax expectation per item.
    float bc[NC], vc[NC];
#pragma unroll
    for (int c = 0; c < NC; c++) { bc[c] = __ldg(cls_b + c); vc[c] = __ldg(values + c); }

    // 100000 % 8 == 0 and (i0+ib) is a multiple of 8 -> whole 8-item group in or out.
    if (i0 + ib < ITEM_NUM) {
        float res[8];
#pragma unroll
        for (int jp = 0; jp < 4; jp++) {
            float2 lc[NC];
#pragma unroll
            for (int c = 0; c < NC; c++) lc[c] = unpack2(acc[jp][c]);
            float num0 = 0.f, den0 = 0.f, num1 = 0.f, den1 = 0.f;
#pragma unroll
            for (int c = 0; c < NC; c++) {
                float e0 = __expf(lc[c].x + bc[c]);
                float e1 = __expf(lc[c].y + bc[c]);
                num0 += e0 * vc[c]; den0 += e0;
                num1 += e1 * vc[c]; den1 += e1;
            }
            res[jp * 2 + 0] = __fdividef(num0, den0);
            res[jp * 2 + 1] = __fdividef(num1, den1);
        }
        float4* o = (float4*)(out + (size_t)(u0 + u) * ITEM_NUM + i0 + ib);
        o[0] = make_float4(res[0], res[1], res[2], res[3]);
        o[1] = make_float4(res[4], res[5], res[6], res[7]);
    }
}

extern "C" void kernel_launch(void* const* d_in, const int* in_sizes, int n_in,
                              void* d_out, int out_size) {
    const void*  batch_user = d_in[0];
    const float* user_table = (const float*)d_in[1];
    const float* item_table = (const float*)d_in[2];
    const float* cls_w      = (const float*)d_in[3];
    const float* cls_b      = (const float*)d_in[4];
    const float* values     = (const float*)d_in[5];
    float* out = (float*)d_out;

    precompute_kernel<<<BS, DIM>>>(batch_user, user_table, cls_w);

    dim3 grid((ITEM_NUM + IT - 1) / IT, BS / UT);  // (1563, 16)
    score_kernel<<<grid, THREADS>>>(item_table, cls_b, values, out);
}

// round 3
// speedup vs baseline: 8.4458x; 8.4458x over previous
#include <cuda_runtime.h>
#include <cuda_bf16.h>
#include <cstdint>

#define ITEM_NUM 100000
#define DIM 64
#define BS 256
#define NC 5

#define M_TILE 128
#define UPC 16                 // users per chunk
#define NCH (NC * UPC)         // 80 N-columns per chunk
#define CHUNKS (BS / UPC)      // 16
#define THREADS 128            // 4 warps, each owns 32 item rows
#define BROW 144               // padded B row bytes (64 bf16 + 8 pad) -> conflict-free ldmatrix

// Precomputed B[chunk][row = c*16+uu][k] = user_emb[k]*W[c][k], bf16. 160 KB (L2-resident).
__device__ __nv_bfloat16 g_B[CHUNKS * NCH * DIM];

__global__ void precompute_B(const void* __restrict__ batch_user,
                             const float* __restrict__ user_table,
                             const float* __restrict__ cls_w) {
    int r = blockIdx.x;    // 0..1279
    int k = threadIdx.x;   // 0..63
    int chunk = r / NCH;
    int row   = r % NCH;
    int c  = row / UPC;
    int uu = row % UPC;
    int slot = chunk * UPC + uu;

    // int64-vs-int32 sniff: ids < 1e5 -> high words zero when int64.
    const unsigned* q = (const unsigned*)batch_user;
    bool is64 = ((q[1] | q[3] | q[5] | q[7]) == 0u);
    long long uid = is64 ? ((const long long*)batch_user)[slot]
                         : (long long)((const int*)batch_user)[slot];

    g_B[(size_t)r * DIM + k] =
        __float2bfloat16(user_table[uid * DIM + k] * cls_w[c * DIM + k]);
}

__device__ __forceinline__ uint32_t smem_u32(const void* p) {
    uint32_t a;
    asm("{ .reg .u64 t; cvta.to.shared.u64 t, %1; cvt.u32.u64 %0, t; }" : "=r"(a) : "l"(p));
    return a;
}
__device__ __forceinline__ void ldsm4(uint32_t* r, uint32_t addr) {
    asm volatile("ldmatrix.sync.aligned.m8n8.x4.shared.b16 {%0,%1,%2,%3}, [%4];"
                 : "=r"(r[0]), "=r"(r[1]), "=r"(r[2]), "=r"(r[3]) : "r"(addr));
}
__device__ __forceinline__ void mma16816(float* d, const uint32_t* a,
                                         uint32_t b0, uint32_t b1) {
    asm volatile(
        "mma.sync.aligned.m16n8k16.row.col.f32.bf16.bf16.f32 "
        "{%0,%1,%2,%3}, {%4,%5,%6,%7}, {%8,%9}, {%0,%1,%2,%3};"
        : "+f"(d[0]), "+f"(d[1]), "+f"(d[2]), "+f"(d[3])
        : "r"(a[0]), "r"(a[1]), "r"(a[2]), "r"(a[3]), "r"(b0), "r"(b1));
}

__global__ __launch_bounds__(THREADS) void score_kernel(
    const float* __restrict__ item_table,
    const float* __restrict__ cls_b,
    const float* __restrict__ values,
    float* __restrict__ out)
{
    __shared__ __align__(16) unsigned char sB[2][NCH * BROW];  // 23040 B

    const int tid = threadIdx.x;
    const int w   = tid >> 5;
    const int t   = tid & 31;
    const int qr  = t >> 2;   // 0..7
    const int qc  = t & 3;    // 0..3
    const int i0  = blockIdx.x * M_TILE;

    // ---- A fragments (items, bf16) once into registers: 2 m-tiles x 4 k-steps x 4 regs ----
    uint32_t afr[2][4][4];
    #pragma unroll
    for (int mt = 0; mt < 2; mt++) {
        int r0 = i0 + w * 32 + mt * 16 + qr;
        int r1 = r0 + 8;
        #pragma unroll
        for (int s = 0; s < 4; s++) {
            int k0 = s * 16 + qc * 2;
            float2 x0 = make_float2(0.f, 0.f), x1 = x0, x2 = x0, x3 = x0;
            if (r0 < ITEM_NUM) {
                x0 = *(const float2*)(item_table + (size_t)r0 * DIM + k0);
                x2 = *(const float2*)(item_table + (size_t)r0 * DIM + k0 + 8);
            }
            if (r1 < ITEM_NUM) {
                x1 = *(const float2*)(item_table + (size_t)r1 * DIM + k0);
                x3 = *(const float2*)(item_table + (size_t)r1 * DIM + k0 + 8);
            }
            __nv_bfloat162 b0 = __float22bfloat162_rn(x0);
            __nv_bfloat162 b1 = __float22bfloat162_rn(x1);
            __nv_bfloat162 b2 = __float22bfloat162_rn(x2);
            __nv_bfloat162 b3 = __float22bfloat162_rn(x3);
            afr[mt][s][0] = *(uint32_t*)&b0;
            afr[mt][s][1] = *(uint32_t*)&b1;
            afr[mt][s][2] = *(uint32_t*)&b2;
            afr[mt][s][3] = *(uint32_t*)&b3;
        }
    }

    // ---- softmax constants (factor out class 0) ----
    float v0 = __ldg(values);
    float bb0 = __ldg(cls_b);
    float vv[NC - 1], db[NC - 1];
    #pragma unroll
    for (int c = 1; c < NC; c++) {
        vv[c - 1] = __ldg(values + c);
        db[c - 1] = __ldg(cls_b + c) - bb0;
    }

    const uint32_t sb_u32 = smem_u32(sB);
    const uint32_t lm_lane = (uint32_t)((t & 7) * BROW + (t >> 3) * 16);

    // ---- stage B chunk 0 into buf 0 ----
    {
        const uint32_t* src = (const uint32_t*)g_B;
        #pragma unroll
        for (int it = 0; it < (NCH * 32) / THREADS; it++) {
            int idx = tid + it * THREADS;
            int row = idx >> 5, kc = idx & 31;
            *(uint32_t*)(sB[0] + row * BROW + kc * 4) = src[idx];
        }
    }
    __syncthreads();

    #pragma unroll 1
    for (int j = 0; j < CHUNKS; j++) {
        // Stage next chunk into the other buffer (overlaps MMA on current buffer).
        if (j + 1 < CHUNKS) {
            const uint32_t* src = (const uint32_t*)(g_B + (size_t)(j + 1) * NCH * DIM);
            unsigned char* dst = sB[(j + 1) & 1];
            #pragma unroll
            for (int it = 0; it < (NCH * 32) / THREADS; it++) {
                int idx = tid + it * THREADS;
                int row = idx >> 5, kc = idx & 31;
                *(uint32_t*)(dst + row * BROW + kc * 4) = src[idx];
            }
        }

        float acc[2][NC * 2][4];
        #pragma unroll
        for (int mt = 0; mt < 2; mt++)
            #pragma unroll
            for (int n = 0; n < NC * 2; n++)
                #pragma unroll
                for (int r = 0; r < 4; r++) acc[mt][n][r] = 0.f;

        const uint32_t bufbase = sb_u32 + (uint32_t)((j & 1) * NCH * BROW) + lm_lane;
        #pragma unroll
        for (int n = 0; n < NC * 2; n++) {
            uint32_t ad = bufbase + (uint32_t)(n * 8 * BROW);
            uint32_t b01[4], b23[4];
            ldsm4(b01, ad);        // k-steps 0,1 (matrices: s0h0,s0h1,s1h0,s1h1)
            ldsm4(b23, ad + 64);   // k-steps 2,3
            #pragma unroll
            for (int mt = 0; mt < 2; mt++) {
                mma16816(acc[mt][n], afr[mt][0], b01[0], b01[1]);
                mma16816(acc[mt][n], afr[mt][1], b01[2], b01[3]);
                mma16816(acc[mt][n], afr[mt][2], b23[0], b23[1]);
                mma16816(acc[mt][n], afr[mt][3], b23[2], b23[3]);
            }
        }

        // ---- fused softmax-EV epilogue on register fragments ----
        #pragma unroll
        for (int mt = 0; mt < 2; mt++) {
            #pragma unroll
            for (int rh = 0; rh < 2; rh++) {
                int gi = i0 + w * 32 + mt * 16 + rh * 8 + qr;
                if (gi < ITEM_NUM) {
                    #pragma unroll
                    for (int g = 0; g < 2; g++) {
                        #pragma unroll
                        for (int p = 0; p < 2; p++) {
                            int uu = g * 8 + qc * 2 + p;
                            float l0 = acc[mt][g][rh * 2 + p];
                            float num = v0, den = 1.f;
                            #pragma unroll
                            for (int c = 1; c < NC; c++) {
                                float e = __expf(acc[mt][2 * c + g][rh * 2 + p]
                                                 - l0 + db[c - 1]);
                                num += e * vv[c - 1];
                                den += e;
                            }
                            out[(size_t)(j * UPC + uu) * ITEM_NUM + gi] =
                                __fdividef(num, den);
                        }
                    }
                }
            }
        }
        __syncthreads();   // buf[j&1] free for overwrite; buf[(j+1)&1] staged
    }
}

extern "C" void kernel_launch(void* const* d_in, const int* in_sizes, int n_in,
                              void* d_out, int out_size) {
    const void*  batch_user = d_in[0];
    const float* user_table = (const float*)d_in[1];
    const float* item_table = (const float*)d_in[2];
    const float* cls_w      = (const float*)d_in[3];
    const float* cls_b      = (const float*)d_in[4];
    const float* values     = (const float*)d_in[5];
    float* out = (float*)d_out;

    precompute_B<<<CHUNKS * NCH, DIM>>>(batch_user, user_table, cls_w);

    dim3 grid((ITEM_NUM + M_TILE - 1) / M_TILE);  // 782
    score_kernel<<<grid, THREADS>>>(item_table, cls_b, values, out);
}

// round 4
// speedup vs baseline: 9.6251x; 1.1396x over previous
#include <cuda_runtime.h>
#include <cuda_bf16.h>
#include <cstdint>

#define ITEM_NUM 100000
#define DIM 64
#define BS 256
#define NC 5

#define M_TILE 128
#define UPC 16                 // users per chunk
#define NCH (NC * UPC)         // 80 B-rows per chunk
#define CHUNKS (BS / UPC)      // 16
#define THREADS 128            // 4 warps, each owns 32 item rows
#define BROW 144               // padded B row bytes -> conflict-free ldmatrix
#define LOG2E 1.4426950408889634f

// Precomputed B[chunk][row = c*16+uu][k] = user_emb[k]*W[c][k]*log2(e), bf16.
__device__ __nv_bfloat16 g_B[CHUNKS * NCH * DIM];

__global__ void precompute_B(const void* __restrict__ batch_user,
                             const float* __restrict__ user_table,
                             const float* __restrict__ cls_w) {
    int r = blockIdx.x;    // 0..1279
    int k = threadIdx.x;   // 0..63
    int chunk = r / NCH;
    int row   = r % NCH;
    int c  = row / UPC;
    int uu = row % UPC;
    int slot = chunk * UPC + uu;

    // int64-vs-int32 sniff: ids < 1e5 -> high words zero when int64.
    const unsigned* q = (const unsigned*)batch_user;
    bool is64 = ((q[1] | q[3] | q[5] | q[7]) == 0u);
    long long uid = is64 ? ((const long long*)batch_user)[slot]
                         : (long long)((const int*)batch_user)[slot];

    g_B[(size_t)r * DIM + k] =
        __float2bfloat16(user_table[uid * DIM + k] * cls_w[c * DIM + k] * LOG2E);
}

__device__ __forceinline__ uint32_t smem_u32(const void* p) {
    uint32_t a;
    asm("{ .reg .u64 t; cvta.to.shared.u64 t, %1; cvt.u32.u64 %0, t; }" : "=r"(a) : "l"(p));
    return a;
}
__device__ __forceinline__ void ldsm4(uint32_t* r, uint32_t addr) {
    asm volatile("ldmatrix.sync.aligned.m8n8.x4.shared.b16 {%0,%1,%2,%3}, [%4];"
                 : "=r"(r[0]), "=r"(r[1]), "=r"(r[2]), "=r"(r[3]) : "r"(addr));
}
__device__ __forceinline__ void mma16816(float* d, const uint32_t* a,
                                         uint32_t b0, uint32_t b1) {
    asm volatile(
        "mma.sync.aligned.m16n8k16.row.col.f32.bf16.bf16.f32 "
        "{%0,%1,%2,%3}, {%4,%5,%6,%7}, {%8,%9}, {%0,%1,%2,%3};"
        : "+f"(d[0]), "+f"(d[1]), "+f"(d[2]), "+f"(d[3])
        : "r"(a[0]), "r"(a[1]), "r"(a[2]), "r"(a[3]), "r"(b0), "r"(b1));
}
__device__ __forceinline__ float ex2(float x) {
    float y; asm("ex2.approx.ftz.f32 %0, %1;" : "=f"(y) : "f"(x)); return y;
}
__device__ __forceinline__ float rcpf(float x) {
    float y; asm("rcp.approx.ftz.f32 %0, %1;" : "=f"(y) : "f"(x)); return y;
}

__global__ __launch_bounds__(THREADS, 5) void score_kernel(
    const float* __restrict__ item_table,
    const float* __restrict__ cls_b,
    const float* __restrict__ values,
    float* __restrict__ out)
{
    __shared__ __align__(16) unsigned char sB[2][NCH * BROW];  // 23040 B

    const int tid = threadIdx.x;
    const int w   = tid >> 5;
    const int t   = tid & 31;
    const int qr  = t >> 2;   // 0..7
    const int qc  = t & 3;    // 0..3
    const int i0  = blockIdx.x * M_TILE;

    // ---- A fragments (items, bf16) once into registers: 2 m-tiles x 4 k-steps x 4 regs
    uint32_t afr[2][4][4];
    #pragma unroll
    for (int mt = 0; mt < 2; mt++) {
        int r0 = i0 + w * 32 + mt * 16 + qr;
        int r1 = r0 + 8;
        #pragma unroll
        for (int s = 0; s < 4; s++) {
            int k0 = s * 16 + qc * 2;
            float2 x0 = make_float2(0.f, 0.f), x1 = x0, x2 = x0, x3 = x0;
            if (r0 < ITEM_NUM) {
                x0 = *(const float2*)(item_table + (size_t)r0 * DIM + k0);
                x2 = *(const float2*)(item_table + (size_t)r0 * DIM + k0 + 8);
            }
            if (r1 < ITEM_NUM) {
                x1 = *(const float2*)(item_table + (size_t)r1 * DIM + k0);
                x3 = *(const float2*)(item_table + (size_t)r1 * DIM + k0 + 8);
            }
            __nv_bfloat162 b0 = __float22bfloat162_rn(x0);
            __nv_bfloat162 b1 = __float22bfloat162_rn(x1);
            __nv_bfloat162 b2 = __float22bfloat162_rn(x2);
            __nv_bfloat162 b3 = __float22bfloat162_rn(x3);
            afr[mt][s][0] = *(uint32_t*)&b0;
            afr[mt][s][1] = *(uint32_t*)&b1;
            afr[mt][s][2] = *(uint32_t*)&b2;
            afr[mt][s][3] = *(uint32_t*)&b3;
        }
    }

    // ---- softmax constants (class 0 factored out; log2e folded into B & db2) ----
    float v0  = __ldg(values);
    float bb0 = __ldg(cls_b);
    float wc[NC - 1], db2[NC - 1];
    #pragma unroll
    for (int c = 1; c < NC; c++) {
        wc[c - 1]  = __ldg(values + c) - v0;
        db2[c - 1] = (__ldg(cls_b + c) - bb0) * LOG2E;
    }

    // ---- per-thread output byte offsets (32-bit; output < 4GB) ----
    char* const outc = (char*)out;
    uint32_t ooff[2][2];
    bool valid[2][2];
    #pragma unroll
    for (int mt = 0; mt < 2; mt++)
        #pragma unroll
        for (int rh = 0; rh < 2; rh++) {
            int gi = i0 + w * 32 + mt * 16 + rh * 8 + qr;
            valid[mt][rh] = (gi < ITEM_NUM);
            ooff[mt][rh] = (uint32_t)(((qc * 2) * ITEM_NUM + gi) * 4);
        }

    const uint32_t sb_u32 = smem_u32(sB);
    const uint32_t lm_lane = (uint32_t)((t & 7) * BROW + (t >> 3) * 16);

    // ---- stage B chunk 0 into buf 0 ----
    {
        const uint32_t* src = (const uint32_t*)g_B;
        #pragma unroll
        for (int it = 0; it < (NCH * 32) / THREADS; it++) {
            int idx = tid + it * THREADS;
            *(uint32_t*)(sB[0] + (idx >> 5) * BROW + (idx & 31) * 4) = src[idx];
        }
    }
    __syncthreads();

    #pragma unroll 1
    for (int j = 0; j < CHUNKS; j++) {
        // Stage next chunk into the other buffer (overlaps MMA on current buffer).
        if (j + 1 < CHUNKS) {
            const uint32_t* src = (const uint32_t*)(g_B + (size_t)(j + 1) * NCH * DIM);
            unsigned char* dst = sB[(j + 1) & 1];
            #pragma unroll
            for (int it = 0; it < (NCH * 32) / THREADS; it++) {
                int idx = tid + it * THREADS;
                *(uint32_t*)(dst + (idx >> 5) * BROW + (idx & 31) * 4) = src[idx];
            }
        }

        const uint32_t bufbase = sb_u32 + (uint32_t)((j & 1) * NCH * BROW) + lm_lane;

        #pragma unroll
        for (int g = 0; g < 2; g++) {       // 8-user half of the chunk
            float acc[2][NC][4];
            #pragma unroll
            for (int mt = 0; mt < 2; mt++)
                #pragma unroll
                for (int cc = 0; cc < NC; cc++)
                    #pragma unroll
                    for (int r = 0; r < 4; r++) acc[mt][cc][r] = 0.f;

            #pragma unroll
            for (int cc = 0; cc < NC; cc++) {
                const int n = 2 * cc + g;
                uint32_t ad = bufbase + (uint32_t)(n * 8 * BROW);
                uint32_t b01[4], b23[4];
                ldsm4(b01, ad);        // k-steps 0,1
                ldsm4(b23, ad + 64);   // k-steps 2,3
                #pragma unroll
                for (int mt = 0; mt < 2; mt++) {
                    mma16816(acc[mt][cc], afr[mt][0], b01[0], b01[1]);
                    mma16816(acc[mt][cc], afr[mt][1], b01[2], b01[3]);
                    mma16816(acc[mt][cc], afr[mt][2], b23[0], b23[1]);
                    mma16816(acc[mt][cc], afr[mt][3], b23[2], b23[3]);
                }
            }

            // ---- fused softmax-EV epilogue (exp via raw EX2, log2e pre-folded) ----
            #pragma unroll
            for (int mt = 0; mt < 2; mt++)
                #pragma unroll
                for (int rh = 0; rh < 2; rh++) {
                    if (valid[mt][rh]) {
                        #pragma unroll
                        for (int p = 0; p < 2; p++) {
                            const int idx = rh * 2 + p;
                            float l0 = acc[mt][0][idx];
                            float den = 1.f, s = 0.f;
                            #pragma unroll
                            for (int cc = 1; cc < NC; cc++) {
                                float e = ex2(acc[mt][cc][idx] - l0 + db2[cc - 1]);
                                den += e;
                                s = fmaf(e, wc[cc - 1], s);
                            }
                            float res = fmaf(s, rcpf(den), v0);
                            *(float*)(outc + ooff[mt][rh]
                                      + (uint32_t)((g * 8 + p) * ITEM_NUM * 4)) = res;
                        }
                    }
                }
        }
        __syncthreads();   // staging done; all reads of buf[j&1] complete

        #pragma unroll
        for (int mt = 0; mt < 2; mt++)
            #pragma unroll
            for (int rh = 0; rh < 2; rh++)
                ooff[mt][rh] += (uint32_t)(UPC * ITEM_NUM * 4);
    }
}

extern "C" void kernel_launch(void* const* d_in, const int* in_sizes, int n_in,
                              void* d_out, int out_size) {
    const void*  batch_user = d_in[0];
    const float* user_table = (const float*)d_in[1];
    const float* item_table = (const float*)d_in[2];
    const float* cls_w      = (const float*)d_in[3];
    const float* cls_b      = (const float*)d_in[4];
    const float* values     = (const float*)d_in[5];
    float* out = (float*)d_out;

    precompute_B<<<CHUNKS * NCH, DIM>>>(batch_user, user_table, cls_w);

    dim3 grid((ITEM_NUM + M_TILE - 1) / M_TILE);  // 782
    score_kernel<<<grid, THREADS>>>(item_table, cls_b, values, out);
}